// round 1
// baseline (speedup 1.0000x reference)
#include <cuda_runtime.h>
#include <cuda_bf16.h>
#include <math.h>

#define N_NODES 50000
#define N_EDGES 800000
#define N_GRAPHS 500
#define C 16            // IN_C == HID_C == 16
#define OUT_C 10
#define MLP_HID 25
#define KROWS 26        // 25 MLP rows + 1 bias row (h=1)
#define PROW (KROWS*C)  // 416 floats per node

// ---------------- scratch (static device globals; no allocs allowed) ----------------
__device__ float g_P[(size_t)N_NODES * PROW];     // 83.2 MB
__device__ float g_aggA[N_NODES * C];
__device__ float g_aggB[N_NODES * C];
__device__ float g_deg[N_NODES];
__device__ float g_x1[N_NODES * C];
__device__ float g_pooled[N_GRAPHS * C];
__device__ float g_cnt[N_GRAPHS];
__device__ float g_sc1[2 * MLP_HID];              // [s[25], c[25]] fused BN affine
__device__ float g_sc2[2 * MLP_HID];

// ---------------- zero scratch ----------------
__global__ void zero_kernel() {
    int t = blockIdx.x * blockDim.x + threadIdx.x;
    int stride = gridDim.x * blockDim.x;
    const int NA = N_NODES * C;
    for (int i = t; i < NA; i += stride) { g_aggA[i] = 0.f; g_aggB[i] = 0.f; }
    for (int i = t; i < N_NODES; i += stride) g_deg[i] = 0.f;
    for (int i = t; i < N_GRAPHS * C; i += stride) g_pooled[i] = 0.f;
    for (int i = t; i < N_GRAPHS; i += stride) g_cnt[i] = 0.f;
}

// ---------------- fold BatchNorm(eval) into affine: h = relu(s*dot + c) ----------------
// t = ea@Wa + ba ; bn = g*(t-mu)*rsqrt(var+eps) + bt  =>  s = g*rsqrt(var+eps), c = s*(ba-mu)+bt
__global__ void prep_kernel(const float* __restrict__ b1a, const float* __restrict__ g1,
                            const float* __restrict__ bt1, const float* __restrict__ m1,
                            const float* __restrict__ v1,
                            const float* __restrict__ b2a, const float* __restrict__ g2,
                            const float* __restrict__ bt2, const float* __restrict__ m2,
                            const float* __restrict__ v2) {
    int k = threadIdx.x;
    if (k < MLP_HID) {
        float s1 = g1[k] * rsqrtf(v1[k] + 1e-5f);
        g_sc1[k] = s1;
        g_sc1[MLP_HID + k] = s1 * (b1a[k] - m1[k]) + bt1[k];
        float s2 = g2[k] * rsqrtf(v2[k] + 1e-5f);
        g_sc2[k] = s2;
        g_sc2[MLP_HID + k] = s2 * (b2a[k] - m2[k]) + bt2[k];
    }
}

// ---------------- per-node precompute: P[n,k,o] = sum_i x[n,i]*Wb[k, i*16+o]; row 25 = bias row
// 16 threads per node (one per o), warp = 2 nodes. Wb(+bb) staged in smem.
__global__ void pk_kernel(const float* __restrict__ x, const float* __restrict__ Wb,
                          const float* __restrict__ bb, float* __restrict__ P) {
    __shared__ float Wbs[KROWS * 256];   // 26.6 KB
    for (int i = threadIdx.x; i < MLP_HID * 256; i += blockDim.x) Wbs[i] = Wb[i];
    for (int i = threadIdx.x; i < 256; i += blockDim.x) Wbs[MLP_HID * 256 + i] = bb[i];
    __syncthreads();

    int t = blockIdx.x * blockDim.x + threadIdx.x;   // exact: 50000*16 / 256 = 3125 blocks
    int n = t >> 4;
    int o = t & 15;
    int lanebase = threadIdx.x & 16;

    float xv = x[n * C + o];
    float xr[16];
#pragma unroll
    for (int i = 0; i < 16; i++) xr[i] = __shfl_sync(0xffffffffu, xv, lanebase + i);

    float* Pout = P + (size_t)n * PROW + o;
#pragma unroll
    for (int k = 0; k < KROWS; k++) {
        float acc = 0.f;
#pragma unroll
        for (int i = 0; i < 16; i++) acc = fmaf(xr[i], Wbs[k * 256 + i * 16 + o], acc);
        Pout[k * 16] = acc;
    }
}

// ---------------- edge kernel: h = relu(s*(ea@Wa)+c) (+ h[25]=1), msg = h @ P[src], atomic agg
// 16 lanes per edge; lane o owns output column o. Warp covers 2 edges.
__global__ void edge_kernel(const float* __restrict__ ea, const int* __restrict__ ei,
                            const float* __restrict__ Wa, const float* __restrict__ sc,
                            const float* __restrict__ P, float* __restrict__ agg,
                            float* __restrict__ deg) {
    int t = blockIdx.x * blockDim.x + threadIdx.x;   // exact: 800000*16 / 256 = 50000 blocks
    int e = t >> 4;
    int o = t & 15;
    int lanebase = threadIdx.x & 16;

    int src = ei[e];
    int dst = ei[N_EDGES + e];
    float a0 = ea[e * 3 + 0], a1 = ea[e * 3 + 1], a2 = ea[e * 3 + 2];

    // lane o computes h[o] and h[o+16]
    float h_lo, h_hi;
    {
        int k = o;
        float d = fmaf(a2, Wa[50 + k], fmaf(a1, Wa[25 + k], a0 * Wa[k]));
        h_lo = fmaxf(fmaf(sc[k], d, sc[MLP_HID + k]), 0.f);
        int k2 = o + 16;
        if (k2 < MLP_HID) {
            float d2 = fmaf(a2, Wa[50 + k2], fmaf(a1, Wa[25 + k2], a0 * Wa[k2]));
            h_hi = fmaxf(fmaf(sc[k2], d2, sc[MLP_HID + k2]), 0.f);
        } else {
            h_hi = (k2 == MLP_HID) ? 1.0f : 0.0f;   // k==25: folded bias row
        }
    }

    const float* __restrict__ Prow = P + (size_t)src * PROW + o;
    float acc = 0.f;
#pragma unroll
    for (int k = 0; k < KROWS; k++) {
        int srclane = lanebase + (k & 15);
        float hk = (k < 16) ? __shfl_sync(0xffffffffu, h_lo, srclane)
                            : __shfl_sync(0xffffffffu, h_hi, srclane);
        acc = fmaf(hk, __ldg(Prow + k * 16), acc);
    }

    atomicAdd(&agg[dst * C + o], acc);
    if (deg != nullptr && o == 0) atomicAdd(&deg[dst], 1.0f);
}

// ---------------- node kernel: x = elu(agg/max(deg,1) + x@root + bias); optional fused pooling
__global__ void node_kernel(const float* __restrict__ agg, const float* __restrict__ deg,
                            const float* __restrict__ xin, const float* __restrict__ root,
                            const float* __restrict__ bias, float* __restrict__ xout,
                            const int* __restrict__ batch, float* __restrict__ pooled,
                            float* __restrict__ cnt) {
    int t = blockIdx.x * blockDim.x + threadIdx.x;   // exact: 50000*16 / 256 = 3125 blocks
    int n = t >> 4;
    int o = t & 15;
    int lanebase = threadIdx.x & 16;

    float v = agg[n * C + o] / fmaxf(deg[n], 1.0f);
    float xv = xin[n * C + o];
#pragma unroll
    for (int i = 0; i < 16; i++)
        v = fmaf(__shfl_sync(0xffffffffu, xv, lanebase + i), root[i * 16 + o], v);
    v += bias[o];
    v = (v > 0.f) ? v : expm1f(v);   // ELU(alpha=1)
    xout[n * C + o] = v;

    if (batch != nullptr) {
        int g = batch[n];
        // warp pair-reduce: lane l <-> l^16 hold adjacent nodes; batch is sorted
        int gother = __shfl_xor_sync(0xffffffffu, g, 16);
        float vother = __shfl_xor_sync(0xffffffffu, v, 16);
        bool lower = (lanebase == 0);
        if (gother == g) {
            if (lower) {
                atomicAdd(&pooled[g * C + o], v + vother);
                if (o == 0) atomicAdd(&cnt[g], 2.0f);
            }
        } else {
            atomicAdd(&pooled[g * C + o], v);
            if (o == 0) atomicAdd(&cnt[g], 1.0f);
        }
    }
}

// ---------------- head: out = (pooled/cnt) @ fcW + fcb ----------------
__global__ void final_kernel(const float* __restrict__ fcW, const float* __restrict__ fcb,
                             float* __restrict__ out) {
    int t = blockIdx.x * blockDim.x + threadIdx.x;
    if (t >= N_GRAPHS * OUT_C) return;
    int g = t / OUT_C;
    int o = t % OUT_C;
    float c = fmaxf(g_cnt[g], 1.0f);
    float acc = fcb[o];
#pragma unroll
    for (int i = 0; i < 16; i++) acc = fmaf(g_pooled[g * C + i] / c, fcW[i * OUT_C + o], acc);
    out[g * OUT_C + o] = acc;
}

extern "C" void kernel_launch(void* const* d_in, const int* in_sizes, int n_in,
                              void* d_out, int out_size) {
    const float* x     = (const float*)d_in[0];
    const int*   ei    = (const int*)d_in[1];
    const float* ea    = (const float*)d_in[2];
    const int*   batch = (const int*)d_in[3];
    const float* W1a = (const float*)d_in[4],  *b1a = (const float*)d_in[5];
    const float* g1  = (const float*)d_in[6],  *bt1 = (const float*)d_in[7];
    const float* m1  = (const float*)d_in[8],  *v1  = (const float*)d_in[9];
    const float* W1b = (const float*)d_in[10], *b1b = (const float*)d_in[11];
    const float* root1 = (const float*)d_in[12], *bias1 = (const float*)d_in[13];
    const float* W2a = (const float*)d_in[14], *b2a = (const float*)d_in[15];
    const float* g2  = (const float*)d_in[16], *bt2 = (const float*)d_in[17];
    const float* m2  = (const float*)d_in[18], *v2  = (const float*)d_in[19];
    const float* W2b = (const float*)d_in[20], *b2b = (const float*)d_in[21];
    const float* root2 = (const float*)d_in[22], *bias2 = (const float*)d_in[23];
    const float* fcW = (const float*)d_in[24], *fcb = (const float*)d_in[25];
    float* out = (float*)d_out;

    // device-global raw pointers via unqualified symbol access is not possible host-side;
    // kernels reference the globals directly. Host only needs grid math.
    zero_kernel<<<512, 256>>>();
    prep_kernel<<<1, 32>>>(b1a, g1, bt1, m1, v1, b2a, g2, bt2, m2, v2);

    // ---- layer 1 ----
    {
        float* P = nullptr; cudaGetSymbolAddress((void**)&P, g_P);
        float* aggA = nullptr; cudaGetSymbolAddress((void**)&aggA, g_aggA);
        float* aggB = nullptr; cudaGetSymbolAddress((void**)&aggB, g_aggB);
        float* deg = nullptr; cudaGetSymbolAddress((void**)&deg, g_deg);
        float* x1 = nullptr; cudaGetSymbolAddress((void**)&x1, g_x1);
        float* pooled = nullptr; cudaGetSymbolAddress((void**)&pooled, g_pooled);
        float* cnt = nullptr; cudaGetSymbolAddress((void**)&cnt, g_cnt);
        float* sc1 = nullptr; cudaGetSymbolAddress((void**)&sc1, g_sc1);
        float* sc2 = nullptr; cudaGetSymbolAddress((void**)&sc2, g_sc2);

        pk_kernel<<<(N_NODES * C) / 256, 256>>>(x, W1b, b1b, P);
        edge_kernel<<<(N_EDGES * C) / 256, 256>>>(ea, ei, W1a, sc1, P, aggA, deg);
        node_kernel<<<(N_NODES * C) / 256, 256>>>(aggA, deg, x, root1, bias1, x1,
                                                  nullptr, nullptr, nullptr);

        // ---- layer 2 ----
        pk_kernel<<<(N_NODES * C) / 256, 256>>>(x1, W2b, b2b, P);
        edge_kernel<<<(N_EDGES * C) / 256, 256>>>(ea, ei, W2a, sc2, P, aggB, nullptr);
        node_kernel<<<(N_NODES * C) / 256, 256>>>(aggB, deg, x1, root2, bias2, x1,
                                                  batch, pooled, cnt);
    }

    // ---- head ----
    final_kernel<<<(N_GRAPHS * OUT_C + 255) / 256, 256>>>(fcW, fcb, out);
}

// round 2
// speedup vs baseline: 1.1252x; 1.1252x over previous
#include <cuda_runtime.h>
#include <cuda_bf16.h>
#include <math.h>

#define N_NODES 50000
#define N_EDGES 800000
#define N_GRAPHS 500
#define C 16            // IN_C == HID_C == 16
#define OUT_C 10
#define MLP_HID 25
#define KROWS 26        // 25 MLP rows + 1 bias row (bias is per (i,o): generic row)
#define PROW (KROWS*C)  // 416 floats per node

// ---------------- scratch (static device globals; no allocs allowed) ----------------
__device__ float g_P[(size_t)N_NODES * PROW];     // 83.2 MB
__device__ float g_aggA[N_NODES * C];
__device__ float g_aggB[N_NODES * C];
__device__ float g_deg[N_NODES];
__device__ float g_x1[N_NODES * C];
__device__ float g_pooled[N_GRAPHS * C];
__device__ float g_cnt[N_GRAPHS];
__device__ float g_sc1[2 * MLP_HID];              // [s[25], c[25]] fused BN affine
__device__ float g_sc2[2 * MLP_HID];

// ---------------- zero scratch ----------------
__global__ void zero_kernel() {
    int t = blockIdx.x * blockDim.x + threadIdx.x;
    int stride = gridDim.x * blockDim.x;
    const int NA = N_NODES * C;
    for (int i = t; i < NA; i += stride) { g_aggA[i] = 0.f; g_aggB[i] = 0.f; }
    for (int i = t; i < N_NODES; i += stride) g_deg[i] = 0.f;
    for (int i = t; i < N_GRAPHS * C; i += stride) g_pooled[i] = 0.f;
    for (int i = t; i < N_GRAPHS; i += stride) g_cnt[i] = 0.f;
}

// ---------------- fold BatchNorm(eval) into affine: h = relu(s*dot + c) ----------------
__global__ void prep_kernel(const float* __restrict__ b1a, const float* __restrict__ g1,
                            const float* __restrict__ bt1, const float* __restrict__ m1,
                            const float* __restrict__ v1,
                            const float* __restrict__ b2a, const float* __restrict__ g2,
                            const float* __restrict__ bt2, const float* __restrict__ m2,
                            const float* __restrict__ v2) {
    int k = threadIdx.x;
    if (k < MLP_HID) {
        float s1 = g1[k] * rsqrtf(v1[k] + 1e-5f);
        g_sc1[k] = s1;
        g_sc1[MLP_HID + k] = s1 * (b1a[k] - m1[k]) + bt1[k];
        float s2 = g2[k] * rsqrtf(v2[k] + 1e-5f);
        g_sc2[k] = s2;
        g_sc2[MLP_HID + k] = s2 * (b2a[k] - m2[k]) + bt2[k];
    }
}

// ---------------- per-node precompute: P[n,k,o] = sum_i x[n,i]*Wb[k, i*16+o]
// 4 lanes per node (one per 4-col group), warp = 8 nodes, float4 smem loads + float4 stores.
__global__ void pk_kernel(const float* __restrict__ x, const float* __restrict__ Wb,
                          const float* __restrict__ bb, float* __restrict__ P) {
    __shared__ float Wbs[KROWS * 256];   // 26.6 KB; row 25 = bb (contributes sum_i x_i*bb[i,o])
    for (int i = threadIdx.x; i < MLP_HID * 256; i += blockDim.x) Wbs[i] = Wb[i];
    for (int i = threadIdx.x; i < 256; i += blockDim.x) Wbs[MLP_HID * 256 + i] = bb[i];
    __syncthreads();

    int t = blockIdx.x * blockDim.x + threadIdx.x;
    int n = t >> 2;                 // 4 lanes per node
    int cg = t & 3;                 // column group: cols 4*cg .. 4*cg+3
    if (n >= N_NODES) return;

    // load full x row (redundant across the node's 4 lanes; L1 dedups)
    const float4* xrow = (const float4*)(x + n * C);
    float4 xa = __ldg(xrow + 0), xb = __ldg(xrow + 1), xc = __ldg(xrow + 2), xd = __ldg(xrow + 3);
    float xr[16] = {xa.x,xa.y,xa.z,xa.w, xb.x,xb.y,xb.z,xb.w,
                    xc.x,xc.y,xc.z,xc.w, xd.x,xd.y,xd.z,xd.w};

    float* Pout = P + (size_t)n * PROW;
#pragma unroll
    for (int k = 0; k < KROWS; k++) {
        float4 acc = make_float4(0.f, 0.f, 0.f, 0.f);
#pragma unroll
        for (int i = 0; i < 16; i++) {
            float4 wq = *(const float4*)&Wbs[k * 256 + i * 16 + cg * 4];
            acc.x = fmaf(xr[i], wq.x, acc.x);
            acc.y = fmaf(xr[i], wq.y, acc.y);
            acc.z = fmaf(xr[i], wq.z, acc.z);
            acc.w = fmaf(xr[i], wq.w, acc.w);
        }
        ((float4*)(Pout + k * 16))[cg] = acc;
    }
}

// ---------------- edge kernel ----------------
// 16 lanes per edge, warp = 2 edges. Lane (kslice = l16>>2, cg = l16&3).
// Each lane accumulates float4 over rows k = 4j+kslice with a predicated LDG.128,
// skipping rows where h[k]==0 (ReLU sparsity ~50%). Cross-kslice shfl_xor reduce,
// then one full-warp scalar atomicAdd (col l16).
__global__ void edge_kernel(const float* __restrict__ ea, const int* __restrict__ ei,
                            const float* __restrict__ Wa, const float* __restrict__ sc,
                            const float* __restrict__ P, float* __restrict__ agg,
                            float* __restrict__ deg) {
    int t = blockIdx.x * blockDim.x + threadIdx.x;   // exact: 800000*16 / 256
    int e = t >> 4;
    int l16 = threadIdx.x & 15;
    int lanebase = threadIdx.x & 16;
    int kslice = l16 >> 2;
    int cg = l16 & 3;

    int src = __ldg(&ei[e]);
    int dst = __ldg(&ei[N_EDGES + e]);
    float a0 = __ldg(&ea[e * 3 + 0]), a1 = __ldg(&ea[e * 3 + 1]), a2 = __ldg(&ea[e * 3 + 2]);

    // lane l16 computes h[l16] and h[l16+16] (k=25: generic row incl. folded bb)
    float h_lo, h_hi;
    {
        int k = l16;
        float d = fmaf(a2, Wa[50 + k], fmaf(a1, Wa[25 + k], a0 * Wa[k]));
        h_lo = fmaxf(fmaf(sc[k], d, sc[MLP_HID + k]), 0.f);
        int k2 = l16 + 16;
        if (k2 < MLP_HID) {
            float d2 = fmaf(a2, Wa[50 + k2], fmaf(a1, Wa[25 + k2], a0 * Wa[k2]));
            h_hi = fmaxf(fmaf(sc[k2], d2, sc[MLP_HID + k2]), 0.f);
        } else {
            h_hi = 1.0f;   // k2==25 bias row weight; k2>25 never used (valid check)
        }
    }

    const float* __restrict__ Prow = P + (size_t)src * PROW;
    float4 acc = make_float4(0.f, 0.f, 0.f, 0.f);
#pragma unroll
    for (int j = 0; j < 7; j++) {
        int k = 4 * j + kslice;
        float hk_lo = __shfl_sync(0xffffffffu, h_lo, lanebase + (k & 15));
        float hk_hi = __shfl_sync(0xffffffffu, h_hi, lanebase + (k & 15));
        float hk = (k < 16) ? hk_lo : hk_hi;
        if (k < KROWS && hk != 0.f) {
            float4 p = __ldg((const float4*)(Prow + k * 16 + cg * 4));
            acc.x = fmaf(hk, p.x, acc.x);
            acc.y = fmaf(hk, p.y, acc.y);
            acc.z = fmaf(hk, p.z, acc.z);
            acc.w = fmaf(hk, p.w, acc.w);
        }
    }

    // reduce over kslice lanes (l16 ^4, ^8): afterwards every lane holds full sums for its cg
    acc.x += __shfl_xor_sync(0xffffffffu, acc.x, 4);
    acc.y += __shfl_xor_sync(0xffffffffu, acc.y, 4);
    acc.z += __shfl_xor_sync(0xffffffffu, acc.z, 4);
    acc.w += __shfl_xor_sync(0xffffffffu, acc.w, 4);
    acc.x += __shfl_xor_sync(0xffffffffu, acc.x, 8);
    acc.y += __shfl_xor_sync(0xffffffffu, acc.y, 8);
    acc.z += __shfl_xor_sync(0xffffffffu, acc.z, 8);
    acc.w += __shfl_xor_sync(0xffffffffu, acc.w, 8);

    // redistribute: dest lane l16 wants col l16 = (cg'=l16>>2, comp'=l16&3).
    // source lane s = lanebase + 4*comp' + cg' (s&3==cg'); it sends acc[(s>>2)&3] = acc[comp'].
    float sendv;
    {
        int myk = kslice;  // (l16>>2)
        sendv = (myk == 0) ? acc.x : (myk == 1) ? acc.y : (myk == 2) ? acc.z : acc.w;
    }
    int srclane = lanebase + 4 * (l16 & 3) + (l16 >> 2);
    float v = __shfl_sync(0xffffffffu, sendv, srclane);

    atomicAdd(&agg[dst * C + l16], v);
    if (deg != nullptr && l16 == 0) atomicAdd(&deg[dst], 1.0f);
}

// ---------------- node kernel: x = elu(agg/max(deg,1) + x@root + bias); optional fused pooling
__global__ void node_kernel(const float* __restrict__ agg, const float* __restrict__ deg,
                            const float* __restrict__ xin, const float* __restrict__ root,
                            const float* __restrict__ bias, float* __restrict__ xout,
                            const int* __restrict__ batch, float* __restrict__ pooled,
                            float* __restrict__ cnt) {
    int t = blockIdx.x * blockDim.x + threadIdx.x;   // exact: 50000*16 / 256
    int n = t >> 4;
    int o = t & 15;
    int lanebase = threadIdx.x & 16;

    float v = agg[n * C + o] / fmaxf(deg[n], 1.0f);
    float xv = xin[n * C + o];
#pragma unroll
    for (int i = 0; i < 16; i++)
        v = fmaf(__shfl_sync(0xffffffffu, xv, lanebase + i), root[i * 16 + o], v);
    v += bias[o];
    v = (v > 0.f) ? v : expm1f(v);   // ELU(alpha=1)
    xout[n * C + o] = v;

    if (batch != nullptr) {
        int g = batch[n];
        int gother = __shfl_xor_sync(0xffffffffu, g, 16);
        float vother = __shfl_xor_sync(0xffffffffu, v, 16);
        bool lower = (lanebase == 0);
        if (gother == g) {
            if (lower) {
                atomicAdd(&pooled[g * C + o], v + vother);
                if (o == 0) atomicAdd(&cnt[g], 2.0f);
            }
        } else {
            atomicAdd(&pooled[g * C + o], v);
            if (o == 0) atomicAdd(&cnt[g], 1.0f);
        }
    }
}

// ---------------- head: out = (pooled/cnt) @ fcW + fcb ----------------
__global__ void final_kernel(const float* __restrict__ fcW, const float* __restrict__ fcb,
                             float* __restrict__ out) {
    int t = blockIdx.x * blockDim.x + threadIdx.x;
    if (t >= N_GRAPHS * OUT_C) return;
    int g = t / OUT_C;
    int o = t % OUT_C;
    float c = fmaxf(g_cnt[g], 1.0f);
    float acc = fcb[o];
#pragma unroll
    for (int i = 0; i < 16; i++) acc = fmaf(g_pooled[g * C + i] / c, fcW[i * OUT_C + o], acc);
    out[g * OUT_C + o] = acc;
}

extern "C" void kernel_launch(void* const* d_in, const int* in_sizes, int n_in,
                              void* d_out, int out_size) {
    const float* x     = (const float*)d_in[0];
    const int*   ei    = (const int*)d_in[1];
    const float* ea    = (const float*)d_in[2];
    const int*   batch = (const int*)d_in[3];
    const float* W1a = (const float*)d_in[4],  *b1a = (const float*)d_in[5];
    const float* g1  = (const float*)d_in[6],  *bt1 = (const float*)d_in[7];
    const float* m1  = (const float*)d_in[8],  *v1  = (const float*)d_in[9];
    const float* W1b = (const float*)d_in[10], *b1b = (const float*)d_in[11];
    const float* root1 = (const float*)d_in[12], *bias1 = (const float*)d_in[13];
    const float* W2a = (const float*)d_in[14], *b2a = (const float*)d_in[15];
    const float* g2  = (const float*)d_in[16], *bt2 = (const float*)d_in[17];
    const float* m2  = (const float*)d_in[18], *v2  = (const float*)d_in[19];
    const float* W2b = (const float*)d_in[20], *b2b = (const float*)d_in[21];
    const float* root2 = (const float*)d_in[22], *bias2 = (const float*)d_in[23];
    const float* fcW = (const float*)d_in[24], *fcb = (const float*)d_in[25];
    float* out = (float*)d_out;

    zero_kernel<<<512, 256>>>();
    prep_kernel<<<1, 32>>>(b1a, g1, bt1, m1, v1, b2a, g2, bt2, m2, v2);

    float* P = nullptr; cudaGetSymbolAddress((void**)&P, g_P);
    float* aggA = nullptr; cudaGetSymbolAddress((void**)&aggA, g_aggA);
    float* aggB = nullptr; cudaGetSymbolAddress((void**)&aggB, g_aggB);
    float* deg = nullptr; cudaGetSymbolAddress((void**)&deg, g_deg);
    float* x1 = nullptr; cudaGetSymbolAddress((void**)&x1, g_x1);
    float* pooled = nullptr; cudaGetSymbolAddress((void**)&pooled, g_pooled);
    float* cnt = nullptr; cudaGetSymbolAddress((void**)&cnt, g_cnt);
    float* sc1 = nullptr; cudaGetSymbolAddress((void**)&sc1, g_sc1);
    float* sc2 = nullptr; cudaGetSymbolAddress((void**)&sc2, g_sc2);

    const int PK_GRID = (N_NODES * 4 + 255) / 256;   // 4 lanes per node

    // ---- layer 1 ----
    pk_kernel<<<PK_GRID, 256>>>(x, W1b, b1b, P);
    edge_kernel<<<(N_EDGES * C) / 256, 256>>>(ea, ei, W1a, sc1, P, aggA, deg);
    node_kernel<<<(N_NODES * C) / 256, 256>>>(aggA, deg, x, root1, bias1, x1,
                                              nullptr, nullptr, nullptr);

    // ---- layer 2 ----
    pk_kernel<<<PK_GRID, 256>>>(x1, W2b, b2b, P);
    edge_kernel<<<(N_EDGES * C) / 256, 256>>>(ea, ei, W2a, sc2, P, aggB, nullptr);
    node_kernel<<<(N_NODES * C) / 256, 256>>>(aggB, deg, x1, root2, bias2, x1,
                                              batch, pooled, cnt);

    // ---- head ----
    final_kernel<<<(N_GRAPHS * OUT_C + 255) / 256, 256>>>(fcW, fcb, out);
}

// round 3
// speedup vs baseline: 1.1410x; 1.0140x over previous
#include <cuda_runtime.h>
#include <cuda_bf16.h>
#include <math.h>

#define N_NODES 50000
#define N_EDGES 800000
#define N_GRAPHS 500
#define C 16            // IN_C == HID_C == 16
#define OUT_C 10
#define MLP_HID 25
#define KROWS 26        // 25 MLP rows + 1 bias row
#define PROW (KROWS*C)  // 416 floats per node

// ---------------- scratch (static device globals; no allocs allowed) ----------------
__device__ float g_P[(size_t)N_NODES * PROW];     // 83.2 MB
__device__ float g_aggA[N_NODES * C];
__device__ float g_aggB[N_NODES * C];
__device__ float g_deg[N_NODES];
__device__ float g_x1[N_NODES * C];
__device__ float g_pooled[N_GRAPHS * C];
__device__ float g_cnt[N_GRAPHS];
__device__ float g_sc1[2 * MLP_HID];
__device__ float g_sc2[2 * MLP_HID];

// ---------------- zero scratch ----------------
__global__ void zero_kernel() {
    int t = blockIdx.x * blockDim.x + threadIdx.x;
    int stride = gridDim.x * blockDim.x;
    const int NA = N_NODES * C;
    for (int i = t; i < NA; i += stride) { g_aggA[i] = 0.f; g_aggB[i] = 0.f; }
    for (int i = t; i < N_NODES; i += stride) g_deg[i] = 0.f;
    for (int i = t; i < N_GRAPHS * C; i += stride) g_pooled[i] = 0.f;
    for (int i = t; i < N_GRAPHS; i += stride) g_cnt[i] = 0.f;
}

// ---------------- fold BatchNorm(eval) into affine: h = relu(s*dot + c) ----------------
__global__ void prep_kernel(const float* __restrict__ b1a, const float* __restrict__ g1,
                            const float* __restrict__ bt1, const float* __restrict__ m1,
                            const float* __restrict__ v1,
                            const float* __restrict__ b2a, const float* __restrict__ g2,
                            const float* __restrict__ bt2, const float* __restrict__ m2,
                            const float* __restrict__ v2) {
    int k = threadIdx.x;
    if (k < MLP_HID) {
        float s1 = g1[k] * rsqrtf(v1[k] + 1e-5f);
        g_sc1[k] = s1;
        g_sc1[MLP_HID + k] = s1 * (b1a[k] - m1[k]) + bt1[k];
        float s2 = g2[k] * rsqrtf(v2[k] + 1e-5f);
        g_sc2[k] = s2;
        g_sc2[MLP_HID + k] = s2 * (b2a[k] - m2[k]) + bt2[k];
    }
}

// ---------------- per-node precompute: P[n,k,o] = sum_i x[n,i]*Wb[k, i*16+o]
// 4 lanes per node (one per 4-col group), float4 smem loads + float4 stores.
__global__ void pk_kernel(const float* __restrict__ x, const float* __restrict__ Wb,
                          const float* __restrict__ bb, float* __restrict__ P) {
    __shared__ float Wbs[KROWS * 256];   // 26.6 KB; row 25 = bb
    for (int i = threadIdx.x; i < MLP_HID * 256; i += blockDim.x) Wbs[i] = Wb[i];
    for (int i = threadIdx.x; i < 256; i += blockDim.x) Wbs[MLP_HID * 256 + i] = bb[i];
    __syncthreads();

    int t = blockIdx.x * blockDim.x + threadIdx.x;
    int n = t >> 2;
    int cg = t & 3;
    if (n >= N_NODES) return;

    const float4* xrow = (const float4*)(x + n * C);
    float4 xa = __ldg(xrow + 0), xb = __ldg(xrow + 1), xc = __ldg(xrow + 2), xd = __ldg(xrow + 3);
    float xr[16] = {xa.x,xa.y,xa.z,xa.w, xb.x,xb.y,xb.z,xb.w,
                    xc.x,xc.y,xc.z,xc.w, xd.x,xd.y,xd.z,xd.w};

    float* Pout = P + (size_t)n * PROW;
#pragma unroll
    for (int k = 0; k < KROWS; k++) {
        float4 acc = make_float4(0.f, 0.f, 0.f, 0.f);
#pragma unroll
        for (int i = 0; i < 16; i++) {
            float4 wq = *(const float4*)&Wbs[k * 256 + i * 16 + cg * 4];
            acc.x = fmaf(xr[i], wq.x, acc.x);
            acc.y = fmaf(xr[i], wq.y, acc.y);
            acc.z = fmaf(xr[i], wq.z, acc.z);
            acc.w = fmaf(xr[i], wq.w, acc.w);
        }
        ((float4*)(Pout + k * 16))[cg] = acc;
    }
}

// ---------------- edge kernel ----------------
// 16 lanes per group; each group handles TWO edges (ILP). Grid-stride persistent.
// Lane (kslice=l16>>2, cg=l16&3). hk precomputed via 1 shfl per (row-group, edge);
// predicated float4 loads skip h==0 rows (~50%). Butterfly reduce + scalar atomics.
__global__ void __launch_bounds__(256) edge_kernel(
        const float* __restrict__ ea, const int* __restrict__ ei,
        const float* __restrict__ Wa, const float* __restrict__ sc,
        const float* __restrict__ P, float* __restrict__ agg,
        float* __restrict__ deg) {
    const int l16 = threadIdx.x & 15;
    const int lanebase = threadIdx.x & 16;
    const int kslice = l16 >> 2;
    const int cg = l16 & 3;

    // per-lane uniform MLP params (lane l16 owns rows l16 and l16+16)
    const float wa_lo0 = __ldg(&Wa[l16]);
    const float wa_lo1 = __ldg(&Wa[25 + l16]);
    const float wa_lo2 = __ldg(&Wa[50 + l16]);
    const float s_lo = __ldg(&sc[l16]);
    const float c_lo = __ldg(&sc[MLP_HID + l16]);
    const int k2 = l16 + 16;
    float wa_hi0 = 0.f, wa_hi1 = 0.f, wa_hi2 = 0.f, s_hi = 0.f, c_hi = 0.f;
    if (k2 < MLP_HID) {
        wa_hi0 = __ldg(&Wa[k2]); wa_hi1 = __ldg(&Wa[25 + k2]); wa_hi2 = __ldg(&Wa[50 + k2]);
        s_hi = __ldg(&sc[k2]); c_hi = __ldg(&sc[MLP_HID + k2]);
    }
    const float hi_const = (k2 == MLP_HID) ? 1.0f : 0.0f;  // row 25 = bias row; 26,27 = 0

    const int ngroups = N_EDGES / 2;
    const int gstride = (gridDim.x * blockDim.x) >> 4;
    for (int g = (blockIdx.x * blockDim.x + threadIdx.x) >> 4; g < ngroups; g += gstride) {
        const int e0 = g * 2, e1 = e0 + 1;
        const int src0 = __ldg(&ei[e0]), src1 = __ldg(&ei[e1]);
        const int dst0 = __ldg(&ei[N_EDGES + e0]), dst1 = __ldg(&ei[N_EDGES + e1]);
        const float a00 = __ldg(&ea[e0 * 3 + 0]), a01 = __ldg(&ea[e0 * 3 + 1]), a02 = __ldg(&ea[e0 * 3 + 2]);
        const float a10 = __ldg(&ea[e1 * 3 + 0]), a11 = __ldg(&ea[e1 * 3 + 1]), a12 = __ldg(&ea[e1 * 3 + 2]);

        float h0_lo = fmaxf(fmaf(s_lo, fmaf(a02, wa_lo2, fmaf(a01, wa_lo1, a00 * wa_lo0)), c_lo), 0.f);
        float h1_lo = fmaxf(fmaf(s_lo, fmaf(a12, wa_lo2, fmaf(a11, wa_lo1, a10 * wa_lo0)), c_lo), 0.f);
        float h0_hi, h1_hi;
        if (k2 < MLP_HID) {
            h0_hi = fmaxf(fmaf(s_hi, fmaf(a02, wa_hi2, fmaf(a01, wa_hi1, a00 * wa_hi0)), c_hi), 0.f);
            h1_hi = fmaxf(fmaf(s_hi, fmaf(a12, wa_hi2, fmaf(a11, wa_hi1, a10 * wa_hi0)), c_hi), 0.f);
        } else {
            h0_hi = hi_const;
            h1_hi = hi_const;
        }

        // broadcast h[k] for rows k = 4j+kslice (one shfl per edge per j)
        float hk0[7], hk1[7];
#pragma unroll
        for (int j = 0; j < 7; j++) {
            const int k = 4 * j + kslice;
            const int sl = lanebase + (k & 15);
            hk0[j] = __shfl_sync(0xffffffffu, (j < 4) ? h0_lo : h0_hi, sl);
            hk1[j] = __shfl_sync(0xffffffffu, (j < 4) ? h1_lo : h1_hi, sl);
        }

        const float4* __restrict__ P0 = (const float4*)(P + (size_t)src0 * PROW) + cg;
        const float4* __restrict__ P1 = (const float4*)(P + (size_t)src1 * PROW) + cg;
        float4 acc0 = make_float4(0.f, 0.f, 0.f, 0.f);
        float4 acc1 = make_float4(0.f, 0.f, 0.f, 0.f);
#pragma unroll
        for (int j = 0; j < 7; j++) {
            const int k = 4 * j + kslice;
            if (hk0[j] != 0.f) {
                float4 p = __ldg(P0 + k * 4);
                acc0.x = fmaf(hk0[j], p.x, acc0.x);
                acc0.y = fmaf(hk0[j], p.y, acc0.y);
                acc0.z = fmaf(hk0[j], p.z, acc0.z);
                acc0.w = fmaf(hk0[j], p.w, acc0.w);
            }
            if (hk1[j] != 0.f) {
                float4 p = __ldg(P1 + k * 4);
                acc1.x = fmaf(hk1[j], p.x, acc1.x);
                acc1.y = fmaf(hk1[j], p.y, acc1.y);
                acc1.z = fmaf(hk1[j], p.z, acc1.z);
                acc1.w = fmaf(hk1[j], p.w, acc1.w);
            }
        }

        // butterfly reduce over kslice lanes (^4, ^8)
#pragma unroll
        for (int m = 4; m <= 8; m <<= 1) {
            acc0.x += __shfl_xor_sync(0xffffffffu, acc0.x, m);
            acc0.y += __shfl_xor_sync(0xffffffffu, acc0.y, m);
            acc0.z += __shfl_xor_sync(0xffffffffu, acc0.z, m);
            acc0.w += __shfl_xor_sync(0xffffffffu, acc0.w, m);
            acc1.x += __shfl_xor_sync(0xffffffffu, acc1.x, m);
            acc1.y += __shfl_xor_sync(0xffffffffu, acc1.y, m);
            acc1.z += __shfl_xor_sync(0xffffffffu, acc1.z, m);
            acc1.w += __shfl_xor_sync(0xffffffffu, acc1.w, m);
        }

        // redistribute so lane l16 holds column l16 (verified mapping from R2)
        const float send0 = (kslice == 0) ? acc0.x : (kslice == 1) ? acc0.y
                           : (kslice == 2) ? acc0.z : acc0.w;
        const float send1 = (kslice == 0) ? acc1.x : (kslice == 1) ? acc1.y
                           : (kslice == 2) ? acc1.z : acc1.w;
        const int srcl = lanebase + 4 * (l16 & 3) + (l16 >> 2);
        const float v0 = __shfl_sync(0xffffffffu, send0, srcl);
        const float v1 = __shfl_sync(0xffffffffu, send1, srcl);

        atomicAdd(&agg[dst0 * C + l16], v0);
        atomicAdd(&agg[dst1 * C + l16], v1);
        if (deg != nullptr && l16 < 2) atomicAdd(&deg[(l16 == 0) ? dst0 : dst1], 1.0f);
    }
}

// ---------------- node kernel: x = elu(agg/max(deg,1) + x@root + bias); optional fused pooling
__global__ void node_kernel(const float* __restrict__ agg, const float* __restrict__ deg,
                            const float* __restrict__ xin, const float* __restrict__ root,
                            const float* __restrict__ bias, float* __restrict__ xout,
                            const int* __restrict__ batch, float* __restrict__ pooled,
                            float* __restrict__ cnt) {
    int t = blockIdx.x * blockDim.x + threadIdx.x;
    int n = t >> 4;
    int o = t & 15;
    int lanebase = threadIdx.x & 16;

    float v = agg[n * C + o] / fmaxf(deg[n], 1.0f);
    float xv = xin[n * C + o];
#pragma unroll
    for (int i = 0; i < 16; i++)
        v = fmaf(__shfl_sync(0xffffffffu, xv, lanebase + i), root[i * 16 + o], v);
    v += bias[o];
    v = (v > 0.f) ? v : expm1f(v);   // ELU(alpha=1)
    xout[n * C + o] = v;

    if (batch != nullptr) {
        int g = batch[n];
        int gother = __shfl_xor_sync(0xffffffffu, g, 16);
        float vother = __shfl_xor_sync(0xffffffffu, v, 16);
        bool lower = (lanebase == 0);
        if (gother == g) {
            if (lower) {
                atomicAdd(&pooled[g * C + o], v + vother);
                if (o == 0) atomicAdd(&cnt[g], 2.0f);
            }
        } else {
            atomicAdd(&pooled[g * C + o], v);
            if (o == 0) atomicAdd(&cnt[g], 1.0f);
        }
    }
}

// ---------------- head: out = (pooled/cnt) @ fcW + fcb ----------------
__global__ void final_kernel(const float* __restrict__ fcW, const float* __restrict__ fcb,
                             float* __restrict__ out) {
    int t = blockIdx.x * blockDim.x + threadIdx.x;
    if (t >= N_GRAPHS * OUT_C) return;
    int g = t / OUT_C;
    int o = t % OUT_C;
    float c = fmaxf(g_cnt[g], 1.0f);
    float acc = fcb[o];
#pragma unroll
    for (int i = 0; i < 16; i++) acc = fmaf(g_pooled[g * C + i] / c, fcW[i * OUT_C + o], acc);
    out[g * OUT_C + o] = acc;
}

extern "C" void kernel_launch(void* const* d_in, const int* in_sizes, int n_in,
                              void* d_out, int out_size) {
    const float* x     = (const float*)d_in[0];
    const int*   ei    = (const int*)d_in[1];
    const float* ea    = (const float*)d_in[2];
    const int*   batch = (const int*)d_in[3];
    const float* W1a = (const float*)d_in[4],  *b1a = (const float*)d_in[5];
    const float* g1  = (const float*)d_in[6],  *bt1 = (const float*)d_in[7];
    const float* m1  = (const float*)d_in[8],  *v1  = (const float*)d_in[9];
    const float* W1b = (const float*)d_in[10], *b1b = (const float*)d_in[11];
    const float* root1 = (const float*)d_in[12], *bias1 = (const float*)d_in[13];
    const float* W2a = (const float*)d_in[14], *b2a = (const float*)d_in[15];
    const float* g2  = (const float*)d_in[16], *bt2 = (const float*)d_in[17];
    const float* m2  = (const float*)d_in[18], *v2  = (const float*)d_in[19];
    const float* W2b = (const float*)d_in[20], *b2b = (const float*)d_in[21];
    const float* root2 = (const float*)d_in[22], *bias2 = (const float*)d_in[23];
    const float* fcW = (const float*)d_in[24], *fcb = (const float*)d_in[25];
    float* out = (float*)d_out;

    zero_kernel<<<512, 256>>>();
    prep_kernel<<<1, 32>>>(b1a, g1, bt1, m1, v1, b2a, g2, bt2, m2, v2);

    float* P = nullptr; cudaGetSymbolAddress((void**)&P, g_P);
    float* aggA = nullptr; cudaGetSymbolAddress((void**)&aggA, g_aggA);
    float* aggB = nullptr; cudaGetSymbolAddress((void**)&aggB, g_aggB);
    float* deg = nullptr; cudaGetSymbolAddress((void**)&deg, g_deg);
    float* x1 = nullptr; cudaGetSymbolAddress((void**)&x1, g_x1);
    float* pooled = nullptr; cudaGetSymbolAddress((void**)&pooled, g_pooled);
    float* cnt = nullptr; cudaGetSymbolAddress((void**)&cnt, g_cnt);
    float* sc1 = nullptr; cudaGetSymbolAddress((void**)&sc1, g_sc1);
    float* sc2 = nullptr; cudaGetSymbolAddress((void**)&sc2, g_sc2);

    const int PK_GRID = (N_NODES * 4 + 255) / 256;
    const int EDGE_GRID = 148 * 8;   // persistent grid-stride

    // ---- layer 1 ----
    pk_kernel<<<PK_GRID, 256>>>(x, W1b, b1b, P);
    edge_kernel<<<EDGE_GRID, 256>>>(ea, ei, W1a, sc1, P, aggA, deg);
    node_kernel<<<(N_NODES * C) / 256, 256>>>(aggA, deg, x, root1, bias1, x1,
                                              nullptr, nullptr, nullptr);

    // ---- layer 2 ----
    pk_kernel<<<PK_GRID, 256>>>(x1, W2b, b2b, P);
    edge_kernel<<<EDGE_GRID, 256>>>(ea, ei, W2a, sc2, P, aggB, nullptr);
    node_kernel<<<(N_NODES * C) / 256, 256>>>(aggB, deg, x1, root2, bias2, x1,
                                              batch, pooled, cnt);

    // ---- head ----
    final_kernel<<<(N_GRAPHS * OUT_C + 255) / 256, 256>>>(fcW, fcb, out);
}

// round 4
// speedup vs baseline: 1.2611x; 1.1053x over previous
#include <cuda_runtime.h>
#include <cuda_bf16.h>
#include <math.h>

#define N_NODES 50000
#define N_EDGES 800000
#define N_GRAPHS 500
#define C 16            // IN_C == HID_C == 16
#define OUT_C 10
#define MLP_HID 25
#define KROWS 26        // 25 MLP rows + 1 bias row
#define PROW (KROWS*C)  // 416 floats per node

// ---------------- scratch (static device globals; no allocs allowed) ----------------
__device__ __align__(16) float g_P[(size_t)N_NODES * PROW];     // 83.2 MB
__device__ __align__(16) float g_aggA[N_NODES * C];
__device__ __align__(16) float g_aggB[N_NODES * C];
__device__ float g_deg[N_NODES];
__device__ __align__(16) float g_x1[N_NODES * C];
__device__ float g_pooled[N_GRAPHS * C];
__device__ float g_cnt[N_GRAPHS];
__device__ float g_sc1[2 * MLP_HID];
__device__ float g_sc2[2 * MLP_HID];

// ---------------- zero scratch ----------------
__global__ void zero_kernel() {
    int t = blockIdx.x * blockDim.x + threadIdx.x;
    int stride = gridDim.x * blockDim.x;
    const int NA = N_NODES * C;
    for (int i = t; i < NA; i += stride) { g_aggA[i] = 0.f; g_aggB[i] = 0.f; }
    for (int i = t; i < N_NODES; i += stride) g_deg[i] = 0.f;
    for (int i = t; i < N_GRAPHS * C; i += stride) g_pooled[i] = 0.f;
    for (int i = t; i < N_GRAPHS; i += stride) g_cnt[i] = 0.f;
}

// ---------------- fold BatchNorm(eval) into affine: h = relu(s*dot + c) ----------------
__global__ void prep_kernel(const float* __restrict__ b1a, const float* __restrict__ g1,
                            const float* __restrict__ bt1, const float* __restrict__ m1,
                            const float* __restrict__ v1,
                            const float* __restrict__ b2a, const float* __restrict__ g2,
                            const float* __restrict__ bt2, const float* __restrict__ m2,
                            const float* __restrict__ v2) {
    int k = threadIdx.x;
    if (k < MLP_HID) {
        float s1 = g1[k] * rsqrtf(v1[k] + 1e-5f);
        g_sc1[k] = s1;
        g_sc1[MLP_HID + k] = s1 * (b1a[k] - m1[k]) + bt1[k];
        float s2 = g2[k] * rsqrtf(v2[k] + 1e-5f);
        g_sc2[k] = s2;
        g_sc2[MLP_HID + k] = s2 * (b2a[k] - m2[k]) + bt2[k];
    }
}

// ---------------- per-node precompute: P[n,k,o] = sum_i x[n,i]*Wb[k, i*16+o]
// 4 lanes per NODE-PAIR (one per 4-col group); 2 nodes per thread amortize LDS traffic.
__global__ void pk_kernel(const float* __restrict__ x, const float* __restrict__ Wb,
                          const float* __restrict__ bb, float* __restrict__ P) {
    __shared__ float Wbs[KROWS * 256];   // 26.6 KB; row 25 = bb
    for (int i = threadIdx.x; i < MLP_HID * 256; i += blockDim.x) Wbs[i] = Wb[i];
    for (int i = threadIdx.x; i < 256; i += blockDim.x) Wbs[MLP_HID * 256 + i] = bb[i];
    __syncthreads();

    int t = blockIdx.x * blockDim.x + threadIdx.x;
    int n0 = (t >> 2) * 2;
    int cg = t & 3;
    if (n0 >= N_NODES) return;

    const float4* xrow0 = (const float4*)(x + n0 * C);
    const float4* xrow1 = (const float4*)(x + (n0 + 1) * C);
    float4 a0 = __ldg(xrow0 + 0), b0 = __ldg(xrow0 + 1), c0 = __ldg(xrow0 + 2), d0 = __ldg(xrow0 + 3);
    float4 a1 = __ldg(xrow1 + 0), b1 = __ldg(xrow1 + 1), c1 = __ldg(xrow1 + 2), d1 = __ldg(xrow1 + 3);
    float xr0[16] = {a0.x,a0.y,a0.z,a0.w, b0.x,b0.y,b0.z,b0.w,
                     c0.x,c0.y,c0.z,c0.w, d0.x,d0.y,d0.z,d0.w};
    float xr1[16] = {a1.x,a1.y,a1.z,a1.w, b1.x,b1.y,b1.z,b1.w,
                     c1.x,c1.y,c1.z,c1.w, d1.x,d1.y,d1.z,d1.w};

    float* Pout0 = P + (size_t)n0 * PROW;
    float* Pout1 = Pout0 + PROW;
#pragma unroll
    for (int k = 0; k < KROWS; k++) {
        float4 acc0 = make_float4(0.f, 0.f, 0.f, 0.f);
        float4 acc1 = make_float4(0.f, 0.f, 0.f, 0.f);
#pragma unroll
        for (int i = 0; i < 16; i++) {
            float4 wq = *(const float4*)&Wbs[k * 256 + i * 16 + cg * 4];
            acc0.x = fmaf(xr0[i], wq.x, acc0.x);
            acc0.y = fmaf(xr0[i], wq.y, acc0.y);
            acc0.z = fmaf(xr0[i], wq.z, acc0.z);
            acc0.w = fmaf(xr0[i], wq.w, acc0.w);
            acc1.x = fmaf(xr1[i], wq.x, acc1.x);
            acc1.y = fmaf(xr1[i], wq.y, acc1.y);
            acc1.z = fmaf(xr1[i], wq.z, acc1.z);
            acc1.w = fmaf(xr1[i], wq.w, acc1.w);
        }
        ((float4*)(Pout0 + k * 16))[cg] = acc0;
        ((float4*)(Pout1 + k * 16))[cg] = acc1;
    }
}

// ---------------- edge kernel ----------------
// 16 lanes per group, 2 edges per group, persistent grid-stride.
// Predicated float4 gathers skip h==0 rows; butterfly reduce; ONE red.global.add.v4.f32
// per edge (lanes kslice==0 carry edge0, kslice==1 carry edge1).
__global__ void __launch_bounds__(256) edge_kernel(
        const float* __restrict__ ea, const int* __restrict__ ei,
        const float* __restrict__ Wa, const float* __restrict__ sc,
        const float* __restrict__ P, float* __restrict__ agg,
        float* __restrict__ deg) {
    const int l16 = threadIdx.x & 15;
    const int lanebase = threadIdx.x & 16;
    const int kslice = l16 >> 2;
    const int cg = l16 & 3;

    const float wa_lo0 = __ldg(&Wa[l16]);
    const float wa_lo1 = __ldg(&Wa[25 + l16]);
    const float wa_lo2 = __ldg(&Wa[50 + l16]);
    const float s_lo = __ldg(&sc[l16]);
    const float c_lo = __ldg(&sc[MLP_HID + l16]);
    const int k2 = l16 + 16;
    float wa_hi0 = 0.f, wa_hi1 = 0.f, wa_hi2 = 0.f, s_hi = 0.f, c_hi = 0.f;
    if (k2 < MLP_HID) {
        wa_hi0 = __ldg(&Wa[k2]); wa_hi1 = __ldg(&Wa[25 + k2]); wa_hi2 = __ldg(&Wa[50 + k2]);
        s_hi = __ldg(&sc[k2]); c_hi = __ldg(&sc[MLP_HID + k2]);
    }
    const float hi_const = (k2 == MLP_HID) ? 1.0f : 0.0f;  // row 25 = bias row; 26,27 = 0

    const int ngroups = N_EDGES / 2;
    const int gstride = (gridDim.x * blockDim.x) >> 4;
    for (int g = (blockIdx.x * blockDim.x + threadIdx.x) >> 4; g < ngroups; g += gstride) {
        const int e0 = g * 2, e1 = e0 + 1;
        const int src0 = __ldg(&ei[e0]), src1 = __ldg(&ei[e1]);
        const int dst0 = __ldg(&ei[N_EDGES + e0]), dst1 = __ldg(&ei[N_EDGES + e1]);
        const float a00 = __ldg(&ea[e0 * 3 + 0]), a01 = __ldg(&ea[e0 * 3 + 1]), a02 = __ldg(&ea[e0 * 3 + 2]);
        const float a10 = __ldg(&ea[e1 * 3 + 0]), a11 = __ldg(&ea[e1 * 3 + 1]), a12 = __ldg(&ea[e1 * 3 + 2]);

        float h0_lo = fmaxf(fmaf(s_lo, fmaf(a02, wa_lo2, fmaf(a01, wa_lo1, a00 * wa_lo0)), c_lo), 0.f);
        float h1_lo = fmaxf(fmaf(s_lo, fmaf(a12, wa_lo2, fmaf(a11, wa_lo1, a10 * wa_lo0)), c_lo), 0.f);
        float h0_hi, h1_hi;
        if (k2 < MLP_HID) {
            h0_hi = fmaxf(fmaf(s_hi, fmaf(a02, wa_hi2, fmaf(a01, wa_hi1, a00 * wa_hi0)), c_hi), 0.f);
            h1_hi = fmaxf(fmaf(s_hi, fmaf(a12, wa_hi2, fmaf(a11, wa_hi1, a10 * wa_hi0)), c_hi), 0.f);
        } else {
            h0_hi = hi_const;
            h1_hi = hi_const;
        }

        // broadcast h[k] for rows k = 4j+kslice
        float hk0[7], hk1[7];
#pragma unroll
        for (int j = 0; j < 7; j++) {
            const int k = 4 * j + kslice;
            const int sl = lanebase + (k & 15);
            hk0[j] = __shfl_sync(0xffffffffu, (j < 4) ? h0_lo : h0_hi, sl);
            hk1[j] = __shfl_sync(0xffffffffu, (j < 4) ? h1_lo : h1_hi, sl);
        }

        const float4* __restrict__ P0 = (const float4*)(P + (size_t)src0 * PROW) + cg;
        const float4* __restrict__ P1 = (const float4*)(P + (size_t)src1 * PROW) + cg;
        float4 acc0 = make_float4(0.f, 0.f, 0.f, 0.f);
        float4 acc1 = make_float4(0.f, 0.f, 0.f, 0.f);
#pragma unroll
        for (int j = 0; j < 7; j++) {
            const int k = 4 * j + kslice;
            if (hk0[j] != 0.f) {
                float4 p = __ldg(P0 + k * 4);
                acc0.x = fmaf(hk0[j], p.x, acc0.x);
                acc0.y = fmaf(hk0[j], p.y, acc0.y);
                acc0.z = fmaf(hk0[j], p.z, acc0.z);
                acc0.w = fmaf(hk0[j], p.w, acc0.w);
            }
            if (hk1[j] != 0.f) {
                float4 p = __ldg(P1 + k * 4);
                acc1.x = fmaf(hk1[j], p.x, acc1.x);
                acc1.y = fmaf(hk1[j], p.y, acc1.y);
                acc1.z = fmaf(hk1[j], p.z, acc1.z);
                acc1.w = fmaf(hk1[j], p.w, acc1.w);
            }
        }

        // butterfly reduce over kslice lanes (^4, ^8): all lanes get full col sums for their cg
#pragma unroll
        for (int m = 4; m <= 8; m <<= 1) {
            acc0.x += __shfl_xor_sync(0xffffffffu, acc0.x, m);
            acc0.y += __shfl_xor_sync(0xffffffffu, acc0.y, m);
            acc0.z += __shfl_xor_sync(0xffffffffu, acc0.z, m);
            acc0.w += __shfl_xor_sync(0xffffffffu, acc0.w, m);
            acc1.x += __shfl_xor_sync(0xffffffffu, acc1.x, m);
            acc1.y += __shfl_xor_sync(0xffffffffu, acc1.y, m);
            acc1.z += __shfl_xor_sync(0xffffffffu, acc1.z, m);
            acc1.w += __shfl_xor_sync(0xffffffffu, acc1.w, m);
        }

        // one vector reduction per edge: kslice 0 lanes carry edge0, kslice 1 lanes edge1
        if (kslice < 2) {
            const float4 r = (kslice == 0) ? acc0 : acc1;
            const int rd = (kslice == 0) ? dst0 : dst1;
            float* addr = &agg[rd * C + cg * 4];
            asm volatile("red.global.add.v4.f32 [%0], {%1,%2,%3,%4};"
                         :: "l"(addr), "f"(r.x), "f"(r.y), "f"(r.z), "f"(r.w)
                         : "memory");
        }
        if (deg != nullptr && l16 < 2) atomicAdd(&deg[(l16 == 0) ? dst0 : dst1], 1.0f);
    }
}

// ---------------- node kernel: x = elu(agg/max(deg,1) + x@root + bias); optional fused pooling
__global__ void node_kernel(const float* __restrict__ agg, const float* __restrict__ deg,
                            const float* __restrict__ xin, const float* __restrict__ root,
                            const float* __restrict__ bias, float* __restrict__ xout,
                            const int* __restrict__ batch, float* __restrict__ pooled,
                            float* __restrict__ cnt) {
    int t = blockIdx.x * blockDim.x + threadIdx.x;
    int n = t >> 4;
    int o = t & 15;
    int lanebase = threadIdx.x & 16;

    float v = agg[n * C + o] / fmaxf(deg[n], 1.0f);
    float xv = xin[n * C + o];
#pragma unroll
    for (int i = 0; i < 16; i++)
        v = fmaf(__shfl_sync(0xffffffffu, xv, lanebase + i), root[i * 16 + o], v);
    v += bias[o];
    v = (v > 0.f) ? v : expm1f(v);   // ELU(alpha=1)
    xout[n * C + o] = v;

    if (batch != nullptr) {
        int g = batch[n];
        int gother = __shfl_xor_sync(0xffffffffu, g, 16);
        float vother = __shfl_xor_sync(0xffffffffu, v, 16);
        bool lower = (lanebase == 0);
        if (gother == g) {
            if (lower) {
                atomicAdd(&pooled[g * C + o], v + vother);
                if (o == 0) atomicAdd(&cnt[g], 2.0f);
            }
        } else {
            atomicAdd(&pooled[g * C + o], v);
            if (o == 0) atomicAdd(&cnt[g], 1.0f);
        }
    }
}

// ---------------- head: out = (pooled/cnt) @ fcW + fcb ----------------
__global__ void final_kernel(const float* __restrict__ fcW, const float* __restrict__ fcb,
                             float* __restrict__ out) {
    int t = blockIdx.x * blockDim.x + threadIdx.x;
    if (t >= N_GRAPHS * OUT_C) return;
    int g = t / OUT_C;
    int o = t % OUT_C;
    float c = fmaxf(g_cnt[g], 1.0f);
    float acc = fcb[o];
#pragma unroll
    for (int i = 0; i < 16; i++) acc = fmaf(g_pooled[g * C + i] / c, fcW[i * OUT_C + o], acc);
    out[g * OUT_C + o] = acc;
}

extern "C" void kernel_launch(void* const* d_in, const int* in_sizes, int n_in,
                              void* d_out, int out_size) {
    const float* x     = (const float*)d_in[0];
    const int*   ei    = (const int*)d_in[1];
    const float* ea    = (const float*)d_in[2];
    const int*   batch = (const int*)d_in[3];
    const float* W1a = (const float*)d_in[4],  *b1a = (const float*)d_in[5];
    const float* g1  = (const float*)d_in[6],  *bt1 = (const float*)d_in[7];
    const float* m1  = (const float*)d_in[8],  *v1  = (const float*)d_in[9];
    const float* W1b = (const float*)d_in[10], *b1b = (const float*)d_in[11];
    const float* root1 = (const float*)d_in[12], *bias1 = (const float*)d_in[13];
    const float* W2a = (const float*)d_in[14], *b2a = (const float*)d_in[15];
    const float* g2  = (const float*)d_in[16], *bt2 = (const float*)d_in[17];
    const float* m2  = (const float*)d_in[18], *v2  = (const float*)d_in[19];
    const float* W2b = (const float*)d_in[20], *b2b = (const float*)d_in[21];
    const float* root2 = (const float*)d_in[22], *bias2 = (const float*)d_in[23];
    const float* fcW = (const float*)d_in[24], *fcb = (const float*)d_in[25];
    float* out = (float*)d_out;

    zero_kernel<<<512, 256>>>();
    prep_kernel<<<1, 32>>>(b1a, g1, bt1, m1, v1, b2a, g2, bt2, m2, v2);

    float* P = nullptr; cudaGetSymbolAddress((void**)&P, g_P);
    float* aggA = nullptr; cudaGetSymbolAddress((void**)&aggA, g_aggA);
    float* aggB = nullptr; cudaGetSymbolAddress((void**)&aggB, g_aggB);
    float* deg = nullptr; cudaGetSymbolAddress((void**)&deg, g_deg);
    float* x1 = nullptr; cudaGetSymbolAddress((void**)&x1, g_x1);
    float* pooled = nullptr; cudaGetSymbolAddress((void**)&pooled, g_pooled);
    float* cnt = nullptr; cudaGetSymbolAddress((void**)&cnt, g_cnt);
    float* sc1 = nullptr; cudaGetSymbolAddress((void**)&sc1, g_sc1);
    float* sc2 = nullptr; cudaGetSymbolAddress((void**)&sc2, g_sc2);

    const int PK_GRID = (N_NODES / 2 * 4 + 255) / 256;   // 2 nodes per thread, 4 lanes/node-pair
    const int EDGE_GRID = 148 * 4;   // exactly-resident persistent grid (64 regs -> 4 CTAs/SM)

    // ---- layer 1 ----
    pk_kernel<<<PK_GRID, 256>>>(x, W1b, b1b, P);
    edge_kernel<<<EDGE_GRID, 256>>>(ea, ei, W1a, sc1, P, aggA, deg);
    node_kernel<<<(N_NODES * C) / 256, 256>>>(aggA, deg, x, root1, bias1, x1,
                                              nullptr, nullptr, nullptr);

    // ---- layer 2 ----
    pk_kernel<<<PK_GRID, 256>>>(x1, W2b, b2b, P);
    edge_kernel<<<EDGE_GRID, 256>>>(ea, ei, W2a, sc2, P, aggB, nullptr);
    node_kernel<<<(N_NODES * C) / 256, 256>>>(aggB, deg, x1, root2, bias2, x1,
                                              batch, pooled, cnt);

    // ---- head ----
    final_kernel<<<(N_GRAPHS * OUT_C + 255) / 256, 256>>>(fcW, fcb, out);
}

// round 5
// speedup vs baseline: 1.6899x; 1.3400x over previous
#include <cuda_runtime.h>
#include <cuda_bf16.h>
#include <math.h>

#define N_NODES 50000
#define N_EDGES 800000
#define N_GRAPHS 500
#define C 16            // IN_C == HID_C == 16
#define OUT_C 10
#define MLP_HID 25
#define KROWS 26        // 25 MLP rows + 1 bias row (always weight 1)
#define PROW (KROWS*C)  // 416 floats per node

// ---------------- scratch (static device globals; no allocs allowed) ----------------
__device__ __align__(16) float g_P[(size_t)N_NODES * PROW];     // 83.2 MB
__device__ __align__(16) float g_aggA[N_NODES * C];
__device__ __align__(16) float g_aggB[N_NODES * C];
__device__ float g_deg[N_NODES];
__device__ __align__(16) float g_x1[N_NODES * C];
__device__ __align__(16) float g_pooled[N_GRAPHS * C];
__device__ float g_cnt[N_GRAPHS];
__device__ float g_sc1[2 * MLP_HID];
__device__ float g_sc2[2 * MLP_HID];

// ---------------- zero scratch ----------------
__global__ void zero_kernel() {
    int t = blockIdx.x * blockDim.x + threadIdx.x;
    int stride = gridDim.x * blockDim.x;
    const int NA = N_NODES * C;
    for (int i = t; i < NA; i += stride) { g_aggA[i] = 0.f; g_aggB[i] = 0.f; }
    for (int i = t; i < N_NODES; i += stride) g_deg[i] = 0.f;
    for (int i = t; i < N_GRAPHS * C; i += stride) g_pooled[i] = 0.f;
    for (int i = t; i < N_GRAPHS; i += stride) g_cnt[i] = 0.f;
}

// ---------------- fold BatchNorm(eval) into affine: h = relu(s*dot + c) ----------------
__global__ void prep_kernel(const float* __restrict__ b1a, const float* __restrict__ g1,
                            const float* __restrict__ bt1, const float* __restrict__ m1,
                            const float* __restrict__ v1,
                            const float* __restrict__ b2a, const float* __restrict__ g2,
                            const float* __restrict__ bt2, const float* __restrict__ m2,
                            const float* __restrict__ v2) {
    int k = threadIdx.x;
    if (k < MLP_HID) {
        float s1 = g1[k] * rsqrtf(v1[k] + 1e-5f);
        g_sc1[k] = s1;
        g_sc1[MLP_HID + k] = s1 * (b1a[k] - m1[k]) + bt1[k];
        float s2 = g2[k] * rsqrtf(v2[k] + 1e-5f);
        g_sc2[k] = s2;
        g_sc2[MLP_HID + k] = s2 * (b2a[k] - m2[k]) + bt2[k];
    }
}

// ---------------- per-node precompute: P[n,k,o] = sum_i x[n,i]*Wb[k, i*16+o]
// 4 lanes per NODE-PAIR (one per 4-col group); 2 nodes per thread amortize LDS traffic.
__global__ void pk_kernel(const float* __restrict__ x, const float* __restrict__ Wb,
                          const float* __restrict__ bb, float* __restrict__ P) {
    __shared__ float Wbs[KROWS * 256];   // 26.6 KB; row 25 = bb
    for (int i = threadIdx.x; i < MLP_HID * 256; i += blockDim.x) Wbs[i] = Wb[i];
    for (int i = threadIdx.x; i < 256; i += blockDim.x) Wbs[MLP_HID * 256 + i] = bb[i];
    __syncthreads();

    int t = blockIdx.x * blockDim.x + threadIdx.x;
    int n0 = (t >> 2) * 2;
    int cg = t & 3;
    if (n0 >= N_NODES) return;

    const float4* xrow0 = (const float4*)(x + n0 * C);
    const float4* xrow1 = (const float4*)(x + (n0 + 1) * C);
    float4 a0 = __ldg(xrow0 + 0), b0 = __ldg(xrow0 + 1), c0 = __ldg(xrow0 + 2), d0 = __ldg(xrow0 + 3);
    float4 a1 = __ldg(xrow1 + 0), b1 = __ldg(xrow1 + 1), c1 = __ldg(xrow1 + 2), d1 = __ldg(xrow1 + 3);
    float xr0[16] = {a0.x,a0.y,a0.z,a0.w, b0.x,b0.y,b0.z,b0.w,
                     c0.x,c0.y,c0.z,c0.w, d0.x,d0.y,d0.z,d0.w};
    float xr1[16] = {a1.x,a1.y,a1.z,a1.w, b1.x,b1.y,b1.z,b1.w,
                     c1.x,c1.y,c1.z,c1.w, d1.x,d1.y,d1.z,d1.w};

    float* Pout0 = P + (size_t)n0 * PROW;
    float* Pout1 = Pout0 + PROW;
#pragma unroll
    for (int k = 0; k < KROWS; k++) {
        float4 acc0 = make_float4(0.f, 0.f, 0.f, 0.f);
        float4 acc1 = make_float4(0.f, 0.f, 0.f, 0.f);
#pragma unroll
        for (int i = 0; i < 16; i++) {
            float4 wq = *(const float4*)&Wbs[k * 256 + i * 16 + cg * 4];
            acc0.x = fmaf(xr0[i], wq.x, acc0.x);
            acc0.y = fmaf(xr0[i], wq.y, acc0.y);
            acc0.z = fmaf(xr0[i], wq.z, acc0.z);
            acc0.w = fmaf(xr0[i], wq.w, acc0.w);
            acc1.x = fmaf(xr1[i], wq.x, acc1.x);
            acc1.y = fmaf(xr1[i], wq.y, acc1.y);
            acc1.z = fmaf(xr1[i], wq.z, acc1.z);
            acc1.w = fmaf(xr1[i], wq.w, acc1.w);
        }
        ((float4*)(Pout0 + k * 16))[cg] = acc0;
        ((float4*)(Pout1 + k * 16))[cg] = acc1;
    }
}

// ---------------- edge kernel: SHUFFLE-FREE ----------------
// 4 lanes per edge (lane = column group cg). Each lane recomputes all h[k] locally
// from smem-broadcast params (cheap FMA), predicates the float4 gather on h>0,
// and owns its float4 column sum -> single red.global.add.v4.f32 per warp (8 edges).
__global__ void __launch_bounds__(256, 5) edge_kernel(
        const float* __restrict__ ea, const int* __restrict__ ei,
        const float* __restrict__ Wa, const float* __restrict__ sc,
        const float* __restrict__ P, float* __restrict__ agg,
        float* __restrict__ deg) {
    __shared__ float4 kpar[MLP_HID];   // {wa0, wa1, wa2, s}
    __shared__ float  kc[MLP_HID];
    if (threadIdx.x < MLP_HID) {
        int k = threadIdx.x;
        kpar[k] = make_float4(__ldg(&Wa[k]), __ldg(&Wa[25 + k]), __ldg(&Wa[50 + k]),
                              __ldg(&sc[k]));
        kc[k] = __ldg(&sc[MLP_HID + k]);
    }
    __syncthreads();

    const int cg = threadIdx.x & 3;
    const int estride = (gridDim.x * blockDim.x) >> 2;
    for (int e = (blockIdx.x * blockDim.x + threadIdx.x) >> 2; e < N_EDGES; e += estride) {
        const int src = __ldg(&ei[e]);
        const int dst = __ldg(&ei[N_EDGES + e]);
        const float a0 = __ldg(&ea[e * 3 + 0]);
        const float a1 = __ldg(&ea[e * 3 + 1]);
        const float a2 = __ldg(&ea[e * 3 + 2]);

        const float4* __restrict__ Pp = (const float4*)(P + (size_t)src * PROW) + cg;

        // bias row (k=25) always has weight 1
        float4 acc = __ldg(Pp + 25 * 4);

#pragma unroll
        for (int k = 0; k < MLP_HID; k++) {
            const float4 w = kpar[k];
            const float h = fmaf(w.w, fmaf(a2, w.z, fmaf(a1, w.y, a0 * w.x)), kc[k]);
            if (h > 0.f) {
                const float4 p = __ldg(Pp + k * 4);
                acc.x = fmaf(h, p.x, acc.x);
                acc.y = fmaf(h, p.y, acc.y);
                acc.z = fmaf(h, p.z, acc.z);
                acc.w = fmaf(h, p.w, acc.w);
            }
        }

        float* addr = &agg[dst * C + cg * 4];
        asm volatile("red.global.add.v4.f32 [%0], {%1,%2,%3,%4};"
                     :: "l"(addr), "f"(acc.x), "f"(acc.y), "f"(acc.z), "f"(acc.w)
                     : "memory");
        if (deg != nullptr && cg == 0) atomicAdd(&deg[dst], 1.0f);
    }
}

// ---------------- node kernel: SHUFFLE-FREE. 4 lanes per node.
// x = elu(agg/max(deg,1) + x@root + bias); optional fused pooling (red.v4).
__global__ void node_kernel(const float* __restrict__ agg, const float* __restrict__ deg,
                            const float* __restrict__ xin, const float* __restrict__ root,
                            const float* __restrict__ bias, float* __restrict__ xout,
                            const int* __restrict__ batch, float* __restrict__ pooled,
                            float* __restrict__ cnt) {
    __shared__ float4 root_s[16][4];   // root[i][cg*4..cg*4+3]
    __shared__ float4 bias_s[4];
    if (threadIdx.x < 64) {
        int i = threadIdx.x >> 2, cgi = threadIdx.x & 3;
        root_s[i][cgi] = ((const float4*)(root + i * 16))[cgi];
        if (i == 0) bias_s[cgi] = ((const float4*)bias)[cgi];
    }
    __syncthreads();

    int t = blockIdx.x * blockDim.x + threadIdx.x;
    int n = t >> 2;
    int cg = t & 3;
    if (n >= N_NODES) return;

    const float dinv = 1.0f / fmaxf(deg[n], 1.0f);
    float4 a = ((const float4*)(agg + n * C))[cg];
    float4 v = make_float4(a.x * dinv, a.y * dinv, a.z * dinv, a.w * dinv);

    const float4* xr = (const float4*)(xin + n * C);
    float4 xq[4] = {__ldg(xr + 0), __ldg(xr + 1), __ldg(xr + 2), __ldg(xr + 3)};
    const float* xs = (const float*)xq;
#pragma unroll
    for (int i = 0; i < 16; i++) {
        float4 r = root_s[i][cg];
        v.x = fmaf(xs[i], r.x, v.x);
        v.y = fmaf(xs[i], r.y, v.y);
        v.z = fmaf(xs[i], r.z, v.z);
        v.w = fmaf(xs[i], r.w, v.w);
    }
    float4 b = bias_s[cg];
    v.x += b.x; v.y += b.y; v.z += b.z; v.w += b.w;
    v.x = (v.x > 0.f) ? v.x : expm1f(v.x);
    v.y = (v.y > 0.f) ? v.y : expm1f(v.y);
    v.z = (v.z > 0.f) ? v.z : expm1f(v.z);
    v.w = (v.w > 0.f) ? v.w : expm1f(v.w);

    ((float4*)(xout + n * C))[cg] = v;

    if (batch != nullptr) {
        int g = __ldg(&batch[n]);
        float* addr = &pooled[g * C + cg * 4];
        asm volatile("red.global.add.v4.f32 [%0], {%1,%2,%3,%4};"
                     :: "l"(addr), "f"(v.x), "f"(v.y), "f"(v.z), "f"(v.w)
                     : "memory");
        if (cg == 0) atomicAdd(&cnt[g], 1.0f);
    }
}

// ---------------- head: out = (pooled/cnt) @ fcW + fcb ----------------
__global__ void final_kernel(const float* __restrict__ fcW, const float* __restrict__ fcb,
                             float* __restrict__ out) {
    int t = blockIdx.x * blockDim.x + threadIdx.x;
    if (t >= N_GRAPHS * OUT_C) return;
    int g = t / OUT_C;
    int o = t % OUT_C;
    float c = fmaxf(g_cnt[g], 1.0f);
    float acc = fcb[o];
#pragma unroll
    for (int i = 0; i < 16; i++) acc = fmaf(g_pooled[g * C + i] / c, fcW[i * OUT_C + o], acc);
    out[g * OUT_C + o] = acc;
}

extern "C" void kernel_launch(void* const* d_in, const int* in_sizes, int n_in,
                              void* d_out, int out_size) {
    const float* x     = (const float*)d_in[0];
    const int*   ei    = (const int*)d_in[1];
    const float* ea    = (const float*)d_in[2];
    const int*   batch = (const int*)d_in[3];
    const float* W1a = (const float*)d_in[4],  *b1a = (const float*)d_in[5];
    const float* g1  = (const float*)d_in[6],  *bt1 = (const float*)d_in[7];
    const float* m1  = (const float*)d_in[8],  *v1  = (const float*)d_in[9];
    const float* W1b = (const float*)d_in[10], *b1b = (const float*)d_in[11];
    const float* root1 = (const float*)d_in[12], *bias1 = (const float*)d_in[13];
    const float* W2a = (const float*)d_in[14], *b2a = (const float*)d_in[15];
    const float* g2  = (const float*)d_in[16], *bt2 = (const float*)d_in[17];
    const float* m2  = (const float*)d_in[18], *v2  = (const float*)d_in[19];
    const float* W2b = (const float*)d_in[20], *b2b = (const float*)d_in[21];
    const float* root2 = (const float*)d_in[22], *bias2 = (const float*)d_in[23];
    const float* fcW = (const float*)d_in[24], *fcb = (const float*)d_in[25];
    float* out = (float*)d_out;

    zero_kernel<<<512, 256>>>();
    prep_kernel<<<1, 32>>>(b1a, g1, bt1, m1, v1, b2a, g2, bt2, m2, v2);

    float* P = nullptr; cudaGetSymbolAddress((void**)&P, g_P);
    float* aggA = nullptr; cudaGetSymbolAddress((void**)&aggA, g_aggA);
    float* aggB = nullptr; cudaGetSymbolAddress((void**)&aggB, g_aggB);
    float* deg = nullptr; cudaGetSymbolAddress((void**)&deg, g_deg);
    float* x1 = nullptr; cudaGetSymbolAddress((void**)&x1, g_x1);
    float* pooled = nullptr; cudaGetSymbolAddress((void**)&pooled, g_pooled);
    float* cnt = nullptr; cudaGetSymbolAddress((void**)&cnt, g_cnt);
    float* sc1 = nullptr; cudaGetSymbolAddress((void**)&sc1, g_sc1);
    float* sc2 = nullptr; cudaGetSymbolAddress((void**)&sc2, g_sc2);

    const int PK_GRID = (N_NODES / 2 * 4 + 255) / 256;   // 2 nodes/thread, 4 lanes/node-pair
    const int EDGE_GRID = 148 * 5;                        // persistent, 5 CTAs/SM
    const int NODE_GRID = (N_NODES * 4 + 255) / 256;      // 4 lanes/node

    // ---- layer 1 ----
    pk_kernel<<<PK_GRID, 256>>>(x, W1b, b1b, P);
    edge_kernel<<<EDGE_GRID, 256>>>(ea, ei, W1a, sc1, P, aggA, deg);
    node_kernel<<<NODE_GRID, 256>>>(aggA, deg, x, root1, bias1, x1,
                                    nullptr, nullptr, nullptr);

    // ---- layer 2 ----
    pk_kernel<<<PK_GRID, 256>>>(x1, W2b, b2b, P);
    edge_kernel<<<EDGE_GRID, 256>>>(ea, ei, W2a, sc2, P, aggB, nullptr);
    node_kernel<<<NODE_GRID, 256>>>(aggB, deg, x1, root2, bias2, x1,
                                    batch, pooled, cnt);

    // ---- head ----
    final_kernel<<<(N_GRAPHS * OUT_C + 255) / 256, 256>>>(fcW, fcb, out);
}

// round 7
// speedup vs baseline: 2.1039x; 1.2450x over previous
#include <cuda_runtime.h>
#include <cuda_fp16.h>
#include <math.h>

#define N_NODES 50000
#define N_EDGES 800000
#define N_GRAPHS 500
#define C 16            // IN_C == HID_C == 16
#define OUT_C 10
#define MLP_HID 25
#define KROWS 26        // 25 MLP rows + 1 bias row (always weight 1)
#define PROW (KROWS*C)  // 416 halves per node

// ---------------- scratch (static device globals; no allocs allowed) ----------------
__device__ __align__(16) __half g_Ph[(size_t)N_NODES * PROW];   // 41.6 MB, fits L2
__device__ __align__(16) float g_aggA[N_NODES * C];
__device__ __align__(16) float g_aggB[N_NODES * C];
__device__ float g_deg[N_NODES];
__device__ __align__(16) float g_x1[N_NODES * C];
__device__ __align__(16) float g_pooled[N_GRAPHS * C];
__device__ float g_cnt[N_GRAPHS];
__device__ float g_sc1[2 * MLP_HID];
__device__ float g_sc2[2 * MLP_HID];

// ---------------- zero scratch ----------------
__global__ void zero_kernel() {
    int t = blockIdx.x * blockDim.x + threadIdx.x;
    int stride = gridDim.x * blockDim.x;
    const int NA = N_NODES * C;
    for (int i = t; i < NA; i += stride) { g_aggA[i] = 0.f; g_aggB[i] = 0.f; }
    for (int i = t; i < N_NODES; i += stride) g_deg[i] = 0.f;
    for (int i = t; i < N_GRAPHS * C; i += stride) g_pooled[i] = 0.f;
    for (int i = t; i < N_GRAPHS; i += stride) g_cnt[i] = 0.f;
}

// ---------------- fold BatchNorm(eval) into affine: h = relu(s*dot + c) ----------------
__global__ void prep_kernel(const float* __restrict__ b1a, const float* __restrict__ g1,
                            const float* __restrict__ bt1, const float* __restrict__ m1,
                            const float* __restrict__ v1,
                            const float* __restrict__ b2a, const float* __restrict__ g2,
                            const float* __restrict__ bt2, const float* __restrict__ m2,
                            const float* __restrict__ v2) {
    int k = threadIdx.x;
    if (k < MLP_HID) {
        float s1 = g1[k] * rsqrtf(v1[k] + 1e-5f);
        g_sc1[k] = s1;
        g_sc1[MLP_HID + k] = s1 * (b1a[k] - m1[k]) + bt1[k];
        float s2 = g2[k] * rsqrtf(v2[k] + 1e-5f);
        g_sc2[k] = s2;
        g_sc2[MLP_HID + k] = s2 * (b2a[k] - m2[k]) + bt2[k];
    }
}

// ---------------- per-node precompute: P[n,k,o] = sum_i x[n,i]*Wb[k, i*16+o]  (fp16 out)
// 4 lanes per NODE-PAIR (one per 4-col group); 2 nodes per thread amortize LDS traffic.
__global__ void pk_kernel(const float* __restrict__ x, const float* __restrict__ Wb,
                          const float* __restrict__ bb, __half* __restrict__ P) {
    __shared__ float Wbs[KROWS * 256];   // 26.6 KB; row 25 = bb
    for (int i = threadIdx.x; i < MLP_HID * 256; i += blockDim.x) Wbs[i] = Wb[i];
    for (int i = threadIdx.x; i < 256; i += blockDim.x) Wbs[MLP_HID * 256 + i] = bb[i];
    __syncthreads();

    int t = blockIdx.x * blockDim.x + threadIdx.x;
    int n0 = (t >> 2) * 2;
    int cg = t & 3;
    if (n0 >= N_NODES) return;

    const float4* xrow0 = (const float4*)(x + n0 * C);
    const float4* xrow1 = (const float4*)(x + (n0 + 1) * C);
    float4 a0 = __ldg(xrow0 + 0), b0 = __ldg(xrow0 + 1), c0 = __ldg(xrow0 + 2), d0 = __ldg(xrow0 + 3);
    float4 a1 = __ldg(xrow1 + 0), b1 = __ldg(xrow1 + 1), c1 = __ldg(xrow1 + 2), d1 = __ldg(xrow1 + 3);
    float xr0[16] = {a0.x,a0.y,a0.z,a0.w, b0.x,b0.y,b0.z,b0.w,
                     c0.x,c0.y,c0.z,c0.w, d0.x,d0.y,d0.z,d0.w};
    float xr1[16] = {a1.x,a1.y,a1.z,a1.w, b1.x,b1.y,b1.z,b1.w,
                     c1.x,c1.y,c1.z,c1.w, d1.x,d1.y,d1.z,d1.w};

    __half* Pout0 = P + (size_t)n0 * PROW;
    __half* Pout1 = Pout0 + PROW;
#pragma unroll
    for (int k = 0; k < KROWS; k++) {
        float4 acc0 = make_float4(0.f, 0.f, 0.f, 0.f);
        float4 acc1 = make_float4(0.f, 0.f, 0.f, 0.f);
#pragma unroll
        for (int i = 0; i < 16; i++) {
            float4 wq = *(const float4*)&Wbs[k * 256 + i * 16 + cg * 4];
            acc0.x = fmaf(xr0[i], wq.x, acc0.x);
            acc0.y = fmaf(xr0[i], wq.y, acc0.y);
            acc0.z = fmaf(xr0[i], wq.z, acc0.z);
            acc0.w = fmaf(xr0[i], wq.w, acc0.w);
            acc1.x = fmaf(xr1[i], wq.x, acc1.x);
            acc1.y = fmaf(xr1[i], wq.y, acc1.y);
            acc1.z = fmaf(xr1[i], wq.z, acc1.z);
            acc1.w = fmaf(xr1[i], wq.w, acc1.w);
        }
        // pack 4 fp32 -> 2 half2 -> one 8 B store, cols cg*4..cg*4+3 of row k
        __half2 lo0 = __floats2half2_rn(acc0.x, acc0.y);
        __half2 hi0 = __floats2half2_rn(acc0.z, acc0.w);
        __half2 lo1 = __floats2half2_rn(acc1.x, acc1.y);
        __half2 hi1 = __floats2half2_rn(acc1.z, acc1.w);
        *(uint2*)(Pout0 + k * 16 + cg * 4) =
            make_uint2(*(const unsigned*)&lo0, *(const unsigned*)&hi0);
        *(uint2*)(Pout1 + k * 16 + cg * 4) =
            make_uint2(*(const unsigned*)&lo1, *(const unsigned*)&hi1);
    }
}

// ---------------- edge kernel: SHUFFLE-FREE, fp16 P, 2 lanes/edge ----------------
// Lane = 8-column half (h8). Each lane recomputes all h[k] locally from smem params,
// predicates the 16 B (8-half) gather on h>0, owns 8 fp32 column sums ->
// two red.global.add.v4.f32 per lane.
__global__ void __launch_bounds__(256, 5) edge_kernel(
        const float* __restrict__ ea, const int* __restrict__ ei,
        const float* __restrict__ Wa, const float* __restrict__ sc,
        const __half* __restrict__ P, float* __restrict__ agg,
        float* __restrict__ deg) {
    __shared__ float4 kpar[MLP_HID];   // {wa0, wa1, wa2, s}
    __shared__ float  kc[MLP_HID];
    if (threadIdx.x < MLP_HID) {
        int k = threadIdx.x;
        kpar[k] = make_float4(__ldg(&Wa[k]), __ldg(&Wa[25 + k]), __ldg(&Wa[50 + k]),
                              __ldg(&sc[k]));
        kc[k] = __ldg(&sc[MLP_HID + k]);
    }
    __syncthreads();

    const int h8 = threadIdx.x & 1;                 // which 8-col half
    const int estride = (gridDim.x * blockDim.x) >> 1;
    for (int e = (blockIdx.x * blockDim.x + threadIdx.x) >> 1; e < N_EDGES; e += estride) {
        const int src = __ldg(&ei[e]);
        const int dst = __ldg(&ei[N_EDGES + e]);
        const float a0 = __ldg(&ea[e * 3 + 0]);
        const float a1 = __ldg(&ea[e * 3 + 1]);
        const float a2 = __ldg(&ea[e * 3 + 2]);

        // row k lives at halves [k*16, k*16+16); this lane's 8 halves = one uint4
        const uint4* __restrict__ Pp = (const uint4*)(P + (size_t)src * PROW) + h8;

        // bias row (k=25), weight 1
        float acc0, acc1, acc2, acc3, acc4, acc5, acc6, acc7;
        {
            uint4 q = __ldg(Pp + 25 * 2);
            float2 f0 = __half22float2(*(__half2*)&q.x);
            float2 f1 = __half22float2(*(__half2*)&q.y);
            float2 f2 = __half22float2(*(__half2*)&q.z);
            float2 f3 = __half22float2(*(__half2*)&q.w);
            acc0 = f0.x; acc1 = f0.y; acc2 = f1.x; acc3 = f1.y;
            acc4 = f2.x; acc5 = f2.y; acc6 = f3.x; acc7 = f3.y;
        }

#pragma unroll
        for (int k = 0; k < MLP_HID; k++) {
            const float4 w = kpar[k];
            const float h = fmaf(w.w, fmaf(a2, w.z, fmaf(a1, w.y, a0 * w.x)), kc[k]);
            if (h > 0.f) {
                uint4 q = __ldg(Pp + k * 2);
                float2 f0 = __half22float2(*(__half2*)&q.x);
                float2 f1 = __half22float2(*(__half2*)&q.y);
                float2 f2 = __half22float2(*(__half2*)&q.z);
                float2 f3 = __half22float2(*(__half2*)&q.w);
                acc0 = fmaf(h, f0.x, acc0); acc1 = fmaf(h, f0.y, acc1);
                acc2 = fmaf(h, f1.x, acc2); acc3 = fmaf(h, f1.y, acc3);
                acc4 = fmaf(h, f2.x, acc4); acc5 = fmaf(h, f2.y, acc5);
                acc6 = fmaf(h, f3.x, acc6); acc7 = fmaf(h, f3.y, acc7);
            }
        }

        float* addr = &agg[dst * C + h8 * 8];
        asm volatile("red.global.add.v4.f32 [%0], {%1,%2,%3,%4};"
                     :: "l"(addr), "f"(acc0), "f"(acc1), "f"(acc2), "f"(acc3)
                     : "memory");
        asm volatile("red.global.add.v4.f32 [%0], {%1,%2,%3,%4};"
                     :: "l"(addr + 4), "f"(acc4), "f"(acc5), "f"(acc6), "f"(acc7)
                     : "memory");
        if (deg != nullptr && h8 == 0) atomicAdd(&deg[dst], 1.0f);
    }
}

// ---------------- node kernel: SHUFFLE-FREE. 4 lanes per node.
__global__ void node_kernel(const float* __restrict__ agg, const float* __restrict__ deg,
                            const float* __restrict__ xin, const float* __restrict__ root,
                            const float* __restrict__ bias, float* __restrict__ xout,
                            const int* __restrict__ batch, float* __restrict__ pooled,
                            float* __restrict__ cnt) {
    __shared__ float4 root_s[16][4];
    __shared__ float4 bias_s[4];
    if (threadIdx.x < 64) {
        int i = threadIdx.x >> 2, cgi = threadIdx.x & 3;
        root_s[i][cgi] = ((const float4*)(root + i * 16))[cgi];
        if (i == 0) bias_s[cgi] = ((const float4*)bias)[cgi];
    }
    __syncthreads();

    int t = blockIdx.x * blockDim.x + threadIdx.x;
    int n = t >> 2;
    int cg = t & 3;
    if (n >= N_NODES) return;

    const float dinv = 1.0f / fmaxf(deg[n], 1.0f);
    float4 a = ((const float4*)(agg + n * C))[cg];
    float4 v = make_float4(a.x * dinv, a.y * dinv, a.z * dinv, a.w * dinv);

    const float4* xr = (const float4*)(xin + n * C);
    float4 xq[4] = {__ldg(xr + 0), __ldg(xr + 1), __ldg(xr + 2), __ldg(xr + 3)};
    const float* xs = (const float*)xq;
#pragma unroll
    for (int i = 0; i < 16; i++) {
        float4 r = root_s[i][cg];
        v.x = fmaf(xs[i], r.x, v.x);
        v.y = fmaf(xs[i], r.y, v.y);
        v.z = fmaf(xs[i], r.z, v.z);
        v.w = fmaf(xs[i], r.w, v.w);
    }
    float4 b = bias_s[cg];
    v.x += b.x; v.y += b.y; v.z += b.z; v.w += b.w;
    v.x = (v.x > 0.f) ? v.x : expm1f(v.x);
    v.y = (v.y > 0.f) ? v.y : expm1f(v.y);
    v.z = (v.z > 0.f) ? v.z : expm1f(v.z);
    v.w = (v.w > 0.f) ? v.w : expm1f(v.w);

    ((float4*)(xout + n * C))[cg] = v;

    if (batch != nullptr) {
        int g = __ldg(&batch[n]);
        float* addr = &pooled[g * C + cg * 4];
        asm volatile("red.global.add.v4.f32 [%0], {%1,%2,%3,%4};"
                     :: "l"(addr), "f"(v.x), "f"(v.y), "f"(v.z), "f"(v.w)
                     : "memory");
        if (cg == 0) atomicAdd(&cnt[g], 1.0f);
    }
}

// ---------------- head: out = (pooled/cnt) @ fcW + fcb ----------------
__global__ void final_kernel(const float* __restrict__ fcW, const float* __restrict__ fcb,
                             float* __restrict__ out) {
    int t = blockIdx.x * blockDim.x + threadIdx.x;
    if (t >= N_GRAPHS * OUT_C) return;
    int g = t / OUT_C;
    int o = t % OUT_C;
    float c = fmaxf(g_cnt[g], 1.0f);
    float acc = fcb[o];
#pragma unroll
    for (int i = 0; i < 16; i++) acc = fmaf(g_pooled[g * C + i] / c, fcW[i * OUT_C + o], acc);
    out[g * OUT_C + o] = acc;
}

extern "C" void kernel_launch(void* const* d_in, const int* in_sizes, int n_in,
                              void* d_out, int out_size) {
    const float* x     = (const float*)d_in[0];
    const int*   ei    = (const int*)d_in[1];
    const float* ea    = (const float*)d_in[2];
    const int*   batch = (const int*)d_in[3];
    const float* W1a = (const float*)d_in[4],  *b1a = (const float*)d_in[5];
    const float* g1  = (const float*)d_in[6],  *bt1 = (const float*)d_in[7];
    const float* m1  = (const float*)d_in[8],  *v1  = (const float*)d_in[9];
    const float* W1b = (const float*)d_in[10], *b1b = (const float*)d_in[11];
    const float* root1 = (const float*)d_in[12], *bias1 = (const float*)d_in[13];
    const float* W2a = (const float*)d_in[14], *b2a = (const float*)d_in[15];
    const float* g2  = (const float*)d_in[16], *bt2 = (const float*)d_in[17];
    const float* m2  = (const float*)d_in[18], *v2  = (const float*)d_in[19];
    const float* W2b = (const float*)d_in[20], *b2b = (const float*)d_in[21];
    const float* root2 = (const float*)d_in[22], *bias2 = (const float*)d_in[23];
    const float* fcW = (const float*)d_in[24], *fcb = (const float*)d_in[25];
    float* out = (float*)d_out;

    zero_kernel<<<512, 256>>>();
    prep_kernel<<<1, 32>>>(b1a, g1, bt1, m1, v1, b2a, g2, bt2, m2, v2);

    __half* P = nullptr; cudaGetSymbolAddress((void**)&P, g_Ph);
    float* aggA = nullptr; cudaGetSymbolAddress((void**)&aggA, g_aggA);
    float* aggB = nullptr; cudaGetSymbolAddress((void**)&aggB, g_aggB);
    float* deg = nullptr; cudaGetSymbolAddress((void**)&deg, g_deg);
    float* x1 = nullptr; cudaGetSymbolAddress((void**)&x1, g_x1);
    float* pooled = nullptr; cudaGetSymbolAddress((void**)&pooled, g_pooled);
    float* cnt = nullptr; cudaGetSymbolAddress((void**)&cnt, g_cnt);
    float* sc1 = nullptr; cudaGetSymbolAddress((void**)&sc1, g_sc1);
    float* sc2 = nullptr; cudaGetSymbolAddress((void**)&sc2, g_sc2);

    const int PK_GRID = (N_NODES / 2 * 4 + 255) / 256;   // 2 nodes/thread, 4 lanes/node-pair
    const int EDGE_GRID = 148 * 5;                        // persistent
    const int NODE_GRID = (N_NODES * 4 + 255) / 256;      // 4 lanes/node

    // ---- layer 1 ----
    pk_kernel<<<PK_GRID, 256>>>(x, W1b, b1b, P);
    edge_kernel<<<EDGE_GRID, 256>>>(ea, ei, W1a, sc1, P, aggA, deg);
    node_kernel<<<NODE_GRID, 256>>>(aggA, deg, x, root1, bias1, x1,
                                    nullptr, nullptr, nullptr);

    // ---- layer 2 ----
    pk_kernel<<<PK_GRID, 256>>>(x1, W2b, b2b, P);
    edge_kernel<<<EDGE_GRID, 256>>>(ea, ei, W2a, sc2, P, aggB, nullptr);
    node_kernel<<<NODE_GRID, 256>>>(aggB, deg, x1, root2, bias2, x1,
                                    batch, pooled, cnt);

    // ---- head ----
    final_kernel<<<(N_GRAPHS * OUT_C + 255) / 256, 256>>>(fcW, fcb, out);
}